// round 7
// baseline (speedup 1.0000x reference)
#include <cuda_runtime.h>
#include <cuda_bf16.h>
#include <cstdint>

#define NB 256
#define NH 256
#define NT 512
#define NL 128
#define NCTA 96
#define NTHR 512
#define NTICK (NT + 3)   // 515

// smem byte offsets: A tile 128 rows x 1024B, B tile 64 rows x 1024B
#define OFF_A    0
#define OFF_B    131072
#define ZS_STRIDE 68
#define OFF_ZS   OFF_B                                    // overlays B after MMA
#define OFF_YS   (OFF_B + 128 * ZS_STRIDE * 4)            // after zs
#define SMEM_BYTES (131072 + 65536)                       // 192 KB

// global state
__device__ uint32_t g_H0[2][NB * NH];          // packed (lo<<16)|hi bf16 of h0, [n][k]
__device__ uint32_t g_H1[2][NB * NH];
__device__ float    g_P[2][32][128 * 64];      // layer1 x-partials [buf][pid][r][n]
__device__ float    g_Y[2][8][NB];             // y partials [buf][mu][b]
__device__ unsigned g_arrive;                  // zeroed each launch

// ---------------- helpers ----------------
__device__ __forceinline__ float sigm(float x) {
    return __fdividef(1.0f, 1.0f + __expf(-x));
}
__device__ __forceinline__ float tanh_f(float x) {
    float e = __expf(2.0f * x);
    return 1.0f - __fdividef(2.0f, e + 1.0f);
}
__device__ __forceinline__ uint32_t s2u(const void* p) {
    uint32_t a;
    asm("{.reg .u64 t; cvta.to.shared.u64 t, %1; cvt.u32.u64 %0, t;}" : "=r"(a) : "l"(p));
    return a;
}
__device__ __forceinline__ uint32_t cvt2(float x, float y) {
    uint32_t r;
    asm("cvt.rn.bf16x2.f32 %0, %1, %2;" : "=r"(r) : "f"(y), "f"(x));
    return r;
}
__device__ __forceinline__ float bf_lo(uint32_t u) {
    __nv_bfloat16_raw r; r.x = (unsigned short)(u & 0xffff);
    return __bfloat162float(*(__nv_bfloat16*)&r);
}
__device__ __forceinline__ float bf_hi(uint32_t u) {
    __nv_bfloat16_raw r; r.x = (unsigned short)(u >> 16);
    return __bfloat162float(*(__nv_bfloat16*)&r);
}
__device__ __forceinline__ void split2(float x, float y, uint32_t& hi, uint32_t& lo) {
    hi = cvt2(x, y);
    lo = cvt2(x - bf_lo(hi), y - bf_hi(hi));
}
__device__ __forceinline__ uint32_t packh(float h) {
    uint32_t p = cvt2(h, 0.f);
    uint32_t hb = p & 0xffff;
    float lo = h - bf_lo(p);
    uint32_t l2 = cvt2(lo, 0.f) & 0xffff;
    return (l2 << 16) | hb;
}

__device__ __forceinline__ void ldsm4(uint32_t* r, uint32_t addr) {
    asm volatile("ldmatrix.sync.aligned.m8n8.x4.shared.b16 {%0,%1,%2,%3}, [%4];"
                 : "=r"(r[0]), "=r"(r[1]), "=r"(r[2]), "=r"(r[3]) : "r"(addr));
}
__device__ __forceinline__ void mma16816(float* c, const uint32_t* a, const uint32_t* b) {
    asm volatile(
        "mma.sync.aligned.m16n8k16.row.col.f32.bf16.bf16.f32 "
        "{%0,%1,%2,%3}, {%4,%5,%6,%7}, {%8,%9}, {%0,%1,%2,%3};"
        : "+f"(c[0]), "+f"(c[1]), "+f"(c[2]), "+f"(c[3])
        : "r"(a[0]), "r"(a[1]), "r"(a[2]), "r"(a[3]), "r"(b[0]), "r"(b[1]));
}

__global__ void __launch_bounds__(NTHR, 1)
lstm_mma_kernel(const float* __restrict__ latent,
                const float* __restrict__ W_lh,  const float* __restrict__ b_lh,
                const float* __restrict__ W_hh0, const float* __restrict__ b_ih0,
                const float* __restrict__ b_hh0,
                const float* __restrict__ W_ih1, const float* __restrict__ W_hh1,
                const float* __restrict__ b_ih1, const float* __restrict__ b_hh1,
                const float* __restrict__ W_ho,  const float* __restrict__ b_ho,
                float* __restrict__ out)
{
    extern __shared__ char smem[];
    const uint32_t sbase = s2u(smem);
    const int tid  = threadIdx.x;
    const int warp = tid >> 5;
    const int lane = tid & 31;

    const int bi   = blockIdx.x;
    const int role = bi >> 5;          // 0=hh0, 1=ih1, 2=hh1
    const int pid  = bi & 31;
    const int mu   = pid >> 2;         // unit tile (32 units)
    const int nu   = pid & 3;          // batch tile (64 batches)
    const int nbase = nu * 64;

    // ---- one-time: stage A = [Whi | Wlo] (128 rows x 512 k bf16, swizzled) ----
    {
        const float* Wsrc = (role == 0) ? W_hh0 : (role == 1) ? W_ih1 : W_hh1;
        for (int i = 0; i < 8; i++) {
            int idx = tid + i * NTHR;          // 0..4095
            int r = idx >> 5, kg = idx & 31;   // A-row, 8-col group
            int grow = (r & 3) * 256 + mu * 32 + (r >> 2);
            const float4* gp = (const float4*)(Wsrc + grow * 256 + kg * 8);
            float4 f0 = gp[0], f1 = gp[1];
            uint32_t h0, h1, h2, h3, l0, l1, l2, l3;
            split2(f0.x, f0.y, h0, l0);
            split2(f0.z, f0.w, h1, l1);
            split2(f1.x, f1.y, h2, l2);
            split2(f1.z, f1.w, h3, l3);
            int swr = r & 7;
            *(uint4*)(smem + OFF_A + r * 1024 + ((kg ^ swr) << 4))        = make_uint4(h0, h1, h2, h3);
            *(uint4*)(smem + OFF_A + r * 1024 + (((32 + kg) ^ swr) << 4)) = make_uint4(l0, l1, l2, l3);
        }
    }

    // ---- epilogue-thread constants: thread -> (unit jl, 4-col group cg4) ----
    const int jl  = tid >> 4;          // 0..31
    const int cg4 = tid & 15;          // 0..15 (cols cg4*4 .. +3)
    const int j   = mu * 32 + jl;
    float bias[4] = {0.f, 0.f, 0.f, 0.f};
    if (role == 0) {
#pragma unroll
        for (int g = 0; g < 4; g++) bias[g] = b_ih0[g * NH + j] + b_hh0[g * NH + j];
    } else if (role == 2) {
#pragma unroll
        for (int g = 0; g < 4; g++) bias[g] = b_ih1[g * NH + j] + b_hh1[g * NH + j];
    }
    const float who = W_ho[j];
    const float bho = b_ho[0];

    // ---- init: h_init = latent @ W_lh.T + b_lh (roles 0,2 write h0(0)/h1(0)) ----
    if (role != 1) {
        uint32_t* dst = (role == 0) ? g_H0[0] : g_H1[0];
        for (int i = 0; i < 4; i++) {
            int idx = tid + i * NTHR;                // 0..2047
            int jj = mu * 32 + (idx & 31);
            int nn = nbase + (idx >> 5);
            float acc = b_lh[jj];
            for (int k = 0; k < NL; k += 4) {
                float4 lv = *(const float4*)(latent + nn * NL + k);
                float4 wv = *(const float4*)(W_lh + jj * NL + k);
                acc += lv.x * wv.x + lv.y * wv.y + lv.z * wv.z + lv.w * wv.w;
            }
            __stcg(&dst[nn * NH + jj], packh(acc));
        }
    }

    float cst[4] = {0.f, 0.f, 0.f, 0.f};

    unsigned bar = 0;
    // initial full barrier
    __threadfence();
    __syncthreads();
    if (tid == 0) {
        atomicAdd(&g_arrive, 1u);
        while (*(volatile unsigned*)&g_arrive < (bar + NCTA)) { }
        __threadfence();
    }
    __syncthreads();
    bar += NCTA;

    // ---- per-lane ldmatrix addressing: warp -> (row tile rt, col half ch) ----
    const int rt = warp & 7;           // A rows rt*16..
    const int ch = warp >> 3;          // B cols ch*32..
    const int swk  = lane & 7;
    const uint32_t aBase = sbase + OFF_A + (uint32_t)(rt * 16 + (lane & 15)) * 1024;
    const int aSel = lane >> 4;
    uint32_t bBase[2];
#pragma unroll
    for (int p2 = 0; p2 < 2; p2++)
        bBase[p2] = sbase + OFF_B +
            (uint32_t)(ch * 32 + p2 * 16 + ((lane >> 4) << 3) + (lane & 7)) * 1024;
    const int bSel = (lane >> 3) & 1;

    float* zs = (float*)(smem + OFF_ZS);
    float* ys = (float*)(smem + OFF_YS);

    for (int tick = 1; tick <= NTICK; tick++) {
        const bool active = (role == 0) ? (tick <= NT)
                          : (role == 1) ? (tick >= 2 && tick <= NT + 1)
                                        : (tick >= 3 && tick <= NT + 2);

        if (active) {
            // ---- stage B = [hhi | hlo] (64 n-rows x 512 k bf16, swizzled) ----
            {
                const uint32_t* src = (role == 2) ? g_H1[(tick - 1) & 1]
                                                  : g_H0[(tick - 1) & 1];
                for (int i = 0; i < 4; i++) {
                    int idx = tid + i * NTHR;         // 0..2047
                    int n = idx >> 5, kg = idx & 31;
                    const uint4* gp = (const uint4*)(src + (nbase + n) * NH + kg * 8);
                    uint4 a = __ldcg(gp);
                    uint4 b = __ldcg(gp + 1);
                    uint32_t h0 = __byte_perm(a.x, a.y, 0x5410), h1 = __byte_perm(a.z, a.w, 0x5410);
                    uint32_t h2 = __byte_perm(b.x, b.y, 0x5410), h3 = __byte_perm(b.z, b.w, 0x5410);
                    uint32_t l0 = __byte_perm(a.x, a.y, 0x7632), l1 = __byte_perm(a.z, a.w, 0x7632);
                    uint32_t l2 = __byte_perm(b.x, b.y, 0x7632), l3 = __byte_perm(b.z, b.w, 0x7632);
                    int swn = n & 7;
                    *(uint4*)(smem + OFF_B + n * 1024 + ((kg ^ swn) << 4))        = make_uint4(h0, h1, h2, h3);
                    *(uint4*)(smem + OFF_B + n * 1024 + (((32 + kg) ^ swn) << 4)) = make_uint4(l0, l1, l2, l3);
                }
            }
            __syncthreads();

            // ---- warp MMA: D[16x32] per warp, passes (Whi*Hhi, Whi*Hlo, Wlo*Hhi) ----
            float acc[4][4];
#pragma unroll
            for (int nt = 0; nt < 4; nt++)
#pragma unroll
                for (int q = 0; q < 4; q++) acc[nt][q] = 0.f;

#pragma unroll 2
            for (int ca = 0; ca < 16; ca++) {
                const int c0h = 2 * ca;        // hi half chunk base
                const int c0l = 32 + 2 * ca;   // lo half
                uint32_t ah[4], al[4], bh[2][4], bl[2][4];
                ldsm4(ah, aBase + (((c0h + aSel) ^ swk) << 4));
                ldsm4(al, aBase + (((c0l + aSel) ^ swk) << 4));
#pragma unroll
                for (int p2 = 0; p2 < 2; p2++) {
                    ldsm4(bh[p2], bBase[p2] + (((c0h + bSel) ^ swk) << 4));
                    ldsm4(bl[p2], bBase[p2] + (((c0l + bSel) ^ swk) << 4));
                }
#pragma unroll
                for (int nt = 0; nt < 4; nt++) {
                    const uint32_t* bhf = &bh[nt >> 1][(nt & 1) * 2];
                    const uint32_t* blf = &bl[nt >> 1][(nt & 1) * 2];
                    mma16816(acc[nt], ah, bhf);   // Whi * Hhi
                    mma16816(acc[nt], ah, blf);   // Whi * Hlo
                    mma16816(acc[nt], al, bhf);   // Wlo * Hhi
                }
            }
            __syncthreads();   // B reads done before zs overlays B

            const int row0 = rt * 16 + (lane >> 2);
            const int colb = 2 * (lane & 3);

            if (role == 1) {
                // dump layer1 x-partials to global
                float* Pd = g_P[(tick - 1) & 1][pid];
#pragma unroll
                for (int nt = 0; nt < 4; nt++) {
                    int c = ch * 32 + nt * 8 + colb;
                    __stcg((float2*)(Pd + row0 * 64 + c), make_float2(acc[nt][0], acc[nt][1]));
                    __stcg((float2*)(Pd + (row0 + 8) * 64 + c), make_float2(acc[nt][2], acc[nt][3]));
                }
            } else {
                if (role == 2) {
                    const float* Ps = g_P[tick & 1][pid];
#pragma unroll
                    for (int nt = 0; nt < 4; nt++) {
                        int c = ch * 32 + nt * 8 + colb;
                        float2 p0 = __ldcg((const float2*)(Ps + row0 * 64 + c));
                        float2 p1 = __ldcg((const float2*)(Ps + (row0 + 8) * 64 + c));
                        acc[nt][0] += p0.x; acc[nt][1] += p0.y;
                        acc[nt][2] += p1.x; acc[nt][3] += p1.y;
                    }
                }
#pragma unroll
                for (int nt = 0; nt < 4; nt++) {
                    int c = ch * 32 + nt * 8 + colb;
                    *(float2*)(zs + row0 * ZS_STRIDE + c)       = make_float2(acc[nt][0], acc[nt][1]);
                    *(float2*)(zs + (row0 + 8) * ZS_STRIDE + c) = make_float2(acc[nt][2], acc[nt][3]);
                }
                __syncthreads();

                // ---- gate nonlinearity + state update (512 threads, 4 cols each) ----
                uint32_t* Hd = (role == 0) ? g_H0[tick & 1] : g_H1[tick & 1];
                const int rb = jl * 4;
                float4 zi4 = *(const float4*)(zs + (rb + 0) * ZS_STRIDE + cg4 * 4);
                float4 zf4 = *(const float4*)(zs + (rb + 1) * ZS_STRIDE + cg4 * 4);
                float4 zg4 = *(const float4*)(zs + (rb + 2) * ZS_STRIDE + cg4 * 4);
                float4 zo4 = *(const float4*)(zs + (rb + 3) * ZS_STRIDE + cg4 * 4);
                float ziv[4] = {zi4.x, zi4.y, zi4.z, zi4.w};
                float zfv[4] = {zf4.x, zf4.y, zf4.z, zf4.w};
                float zgv[4] = {zg4.x, zg4.y, zg4.z, zg4.w};
                float zov[4] = {zo4.x, zo4.y, zo4.z, zo4.w};
#pragma unroll
                for (int c = 0; c < 4; c++) {
                    float zi = ziv[c] + bias[0];
                    float zf = zfv[c] + bias[1];
                    float zg = zgv[c] + bias[2];
                    float zo = zov[c] + bias[3];
                    cst[c] = sigm(zf) * cst[c] + sigm(zi) * tanh_f(zg);
                    float h = sigm(zo) * tanh_f(cst[c]);
                    int col = cg4 * 4 + c;
                    __stcg(&Hd[(nbase + col) * NH + j], packh(h));
                    if (role == 2) ys[col * 33 + jl] = h * who;
                }
                if (role == 2) {
                    __syncthreads();
                    if (tid < 64) {
                        float s = 0.f;
#pragma unroll
                        for (int k = 0; k < 32; k++) s += ys[tid * 33 + k];
                        __stcg(&g_Y[tick & 1][mu][nbase + tid], s);
                    }
                }
            }
        }

        // ---- barrier: arrive early, out-summer in the shadow, then wait ----
        __threadfence();
        __syncthreads();
        if (tid == 0) atomicAdd(&g_arrive, 1u);

        if (role == 2 && mu == 0 && tick >= 4 && tid >= 64 && tid < 128) {
            int b = tid - 64;
            float s = bho;
#pragma unroll
            for (int m = 0; m < 8; m++)
                s += __ldcg(&g_Y[(tick - 1) & 1][m][nbase + b]);
            out[(nbase + b) * NT + (tick - 4)] = s;
        }

        bar += NCTA;
        if (tid == 0) {
            while (*(volatile unsigned*)&g_arrive < bar) { }
            __threadfence();
        }
        __syncthreads();
    }
}

extern "C" void kernel_launch(void* const* d_in, const int* in_sizes, int n_in,
                              void* d_out, int out_size)
{
    (void)in_sizes; (void)n_in; (void)out_size;
    cudaFuncSetAttribute(lstm_mma_kernel,
                         cudaFuncAttributeMaxDynamicSharedMemorySize, SMEM_BYTES);
    void* barp = nullptr;
    cudaGetSymbolAddress(&barp, g_arrive);
    cudaMemsetAsync(barp, 0, sizeof(unsigned));

    lstm_mma_kernel<<<NCTA, NTHR, SMEM_BYTES>>>(
        (const float*)d_in[0],   // latent
        (const float*)d_in[1],   // W_lh
        (const float*)d_in[2],   // b_lh
        // d_in[3] = W_ih0 unused (layer-0 input is all-zero)
        (const float*)d_in[4],   // W_hh0
        (const float*)d_in[5],   // b_ih0
        (const float*)d_in[6],   // b_hh0
        (const float*)d_in[7],   // W_ih1
        (const float*)d_in[8],   // W_hh1
        (const float*)d_in[9],   // b_ih1
        (const float*)d_in[10],  // b_hh1
        (const float*)d_in[11],  // W_ho
        (const float*)d_in[12],  // b_ho
        (float*)d_out);
}